// round 5
// baseline (speedup 1.0000x reference)
#include <cuda_runtime.h>
#include <cuda_fp16.h>

#define NN 100000
#define EE 1600000
#define FIN 128
#define HH 64
#define OUTF 32
#define NB_SCAN 98   // ceil(100000/1024)

// ---------------- scratch (device globals; no allocation) ----------------
__device__ float  g_h[NN * HH];       // fp32 gemm output (gemm2 input path)
__device__ __half g_hh[NN * HH];      // fp16 mirror for the edge gather
__device__ float  g_o[NN * HH];
__device__ float  g_asrc[NN];
__device__ float  g_adst[NN];
__device__ int    g_deg[2 * NN];
__device__ int    g_rowptr[2 * (NN + 1)];
__device__ int    g_cursor[2 * NN];
__device__ int    g_csr_src[2 * EE];
__device__ int    g_bsum[2 * 128];

// ---------------- GEMM + fused attention dots + fp16 mirror ----------------
template <int K, bool RELU>
__global__ void gemm_att(const float* __restrict__ X, const float* __restrict__ W,
                         float* __restrict__ Y, __half* __restrict__ Yh,
                         const float* __restrict__ av_s, const float* __restrict__ av_d,
                         int nrows) {
    __shared__ float xs[64][68];
    __shared__ float ws[64][64];
    __shared__ float redp[16][64];
    __shared__ float redd[16][64];
    int tid = threadIdx.x;
    int tn = (tid & 15) * 4;
    int g  = tid >> 4;
    int tc = g * 4;
    int row0 = blockIdx.x * 64;

    float acc[4][4];
#pragma unroll
    for (int i = 0; i < 4; i++)
#pragma unroll
        for (int j = 0; j < 4; j++) acc[i][j] = 0.f;

    for (int k0 = 0; k0 < K; k0 += 64) {
        for (int idx = tid; idx < 64 * 64; idx += 256) {
            int r = idx >> 6, k = idx & 63;
            int row = row0 + r;
            float v = (row < nrows) ? X[row * K + k0 + k] : 0.f;
            if (RELU) v = fmaxf(v, 0.f);
            xs[k][r] = v;
        }
        for (int idx = tid; idx < 64 * 64; idx += 256) {
            int k = idx >> 6, c = idx & 63;
            ws[k][c] = W[(k0 + k) * 64 + c];
        }
        __syncthreads();
#pragma unroll 8
        for (int kk = 0; kk < 64; ++kk) {
            float4 a = *(const float4*)&xs[kk][tn];
            float4 b = *(const float4*)&ws[kk][tc];
            acc[0][0] += a.x * b.x; acc[0][1] += a.x * b.y; acc[0][2] += a.x * b.z; acc[0][3] += a.x * b.w;
            acc[1][0] += a.y * b.x; acc[1][1] += a.y * b.y; acc[1][2] += a.y * b.z; acc[1][3] += a.y * b.w;
            acc[2][0] += a.z * b.x; acc[2][1] += a.z * b.y; acc[2][2] += a.z * b.z; acc[2][3] += a.z * b.w;
            acc[3][0] += a.w * b.x; acc[3][1] += a.w * b.y; acc[3][2] += a.w * b.z; acc[3][3] += a.w * b.w;
        }
        __syncthreads();
    }

    float as0 = av_s[tc], as1 = av_s[tc + 1], as2 = av_s[tc + 2], as3 = av_s[tc + 3];
    float ad0 = av_d[tc], ad1 = av_d[tc + 1], ad2 = av_d[tc + 2], ad3 = av_d[tc + 3];
#pragma unroll
    for (int i = 0; i < 4; i++) {
        int row = row0 + tn + i;
        if (row < nrows) {
            float4 v = make_float4(acc[i][0], acc[i][1], acc[i][2], acc[i][3]);
            *(float4*)&Y[row * 64 + tc] = v;
            __half2 p0 = __floats2half2_rn(acc[i][0], acc[i][1]);
            __half2 p1 = __floats2half2_rn(acc[i][2], acc[i][3]);
            uint2 packed;
            packed.x = *(unsigned*)&p0;
            packed.y = *(unsigned*)&p1;
            *(uint2*)(Yh + row * 64 + tc) = packed;
        }
        redp[g][tn + i] = acc[i][0] * as0 + acc[i][1] * as1 + acc[i][2] * as2 + acc[i][3] * as3;
        redd[g][tn + i] = acc[i][0] * ad0 + acc[i][1] * ad1 + acc[i][2] * ad2 + acc[i][3] * ad3;
    }
    __syncthreads();
    if (tid < 64) {
        int row = row0 + tid;
        float ps = 0.f, pd = 0.f;
#pragma unroll
        for (int c = 0; c < 16; c++) { ps += redp[c][tid]; pd += redd[c][tid]; }
        if (row < nrows) { g_asrc[row] = ps; g_adst[row] = pd; }
    }
}

// ---------------- CSR build (per-graph chains) ----------------
__global__ void zero_k(int L) {
    int i = blockIdx.x * blockDim.x + threadIdx.x;
    if (i < NN) g_deg[L * NN + i] = 0;
}
__global__ void hist_k(const int* __restrict__ e, int L) {
    int i = blockIdx.x * blockDim.x + threadIdx.x;
    if (i < EE) atomicAdd(&g_deg[L * NN + e[EE + i]], 1);
}
__global__ void scan1_k(int L) {
    __shared__ int s[1024];
    int tid = threadIdx.x;
    int i = blockIdx.x * 1024 + tid;
    int v = (i < NN) ? g_deg[L * NN + i] : 0;
    s[tid] = v;
    __syncthreads();
#pragma unroll
    for (int off = 1; off < 1024; off <<= 1) {
        int t = (tid >= off) ? s[tid - off] : 0;
        __syncthreads();
        s[tid] += t;
        __syncthreads();
    }
    if (i < NN) g_rowptr[L * (NN + 1) + i] = s[tid] - v;
    if (tid == 1023) g_bsum[L * 128 + blockIdx.x] = s[1023];
}
__global__ void scan23_k(int L) {
    __shared__ int bpart[128];
    __shared__ int base_s;
    int b = blockIdx.x;
    int tid = threadIdx.x;
    if (tid < 128) bpart[tid] = (tid < b) ? g_bsum[L * 128 + tid] : 0;
    __syncthreads();
    if (tid < 64) bpart[tid] += bpart[tid + 64];
    __syncthreads();
    if (tid < 32) {
        int v = bpart[tid] + bpart[tid + 32];
#pragma unroll
        for (int off = 16; off; off >>= 1) v += __shfl_xor_sync(0xffffffffu, v, off);
        if (tid == 0) base_s = v;
    }
    __syncthreads();
    int i = b * 1024 + tid;
    if (i < NN) {
        int r = g_rowptr[L * (NN + 1) + i] + base_s;
        g_rowptr[L * (NN + 1) + i] = r;
        g_cursor[L * NN + i] = r;
    }
    if (b == 0 && tid == 0) g_rowptr[L * (NN + 1) + NN] = EE;
}
__global__ void scatter_k(const int* __restrict__ e, int L) {
    int i = blockIdx.x * blockDim.x + threadIdx.x;
    if (i < EE) {
        int d = e[EE + i];
        int p = atomicAdd(&g_cursor[L * NN + d], 1);
        g_csr_src[L * EE + p] = e[i];
    }
}

// ---------------- fused segment softmax + aggregate (fp16 gather) ----------
// warp per dst node; half-warp per edge, 8B fp16 loads, 8 edges in flight.
template <bool FINAL>
__global__ void agg_k(const __half* __restrict__ hh, const float* __restrict__ bias,
                      float* __restrict__ out,
                      const int* __restrict__ rowptr, const int* __restrict__ csr,
                      const float* __restrict__ Wl, const float* __restrict__ bl) {
    __shared__ float wsh[64 * 32];
    if (FINAL) {
        for (int i = threadIdx.x; i < 64 * 32; i += 256) wsh[i] = Wl[i];
        __syncthreads();
    }
    int gw = (blockIdx.x * blockDim.x + threadIdx.x) >> 5;
    int lane = threadIdx.x & 31;
    if (gw >= NN) return;
    int half = lane >> 4;
    int q = (lane & 15) * 4;
    int start = rowptr[gw];
    int end = rowptr[gw + 1];
    float ad = g_adst[gw];

    float4 acc = make_float4(0.f, 0.f, 0.f, 0.f);
    float ssum = 0.f;
    for (int j0 = start; j0 < end; j0 += 32) {
        int j = j0 + lane;
        int s = 0; float w = 0.f;
        if (j < end) {
            s = csr[j];
            float e = __ldg(&g_asrc[s]) + ad;
            e = (e >= 0.f) ? e : 0.2f * e;
            w = __expf(e);
        }
        ssum += w;
        int cnt = min(32, end - j0);
        int p2 = 0;
        for (; p2 + 8 <= cnt; p2 += 8) {
            int e0 = p2 + half, e1 = p2 + 2 + half, e2 = p2 + 4 + half, e3 = p2 + 6 + half;
            float w0 = __shfl_sync(0xffffffffu, w, e0);
            int   s0 = __shfl_sync(0xffffffffu, s, e0);
            float w1 = __shfl_sync(0xffffffffu, w, e1);
            int   s1 = __shfl_sync(0xffffffffu, s, e1);
            float w2 = __shfl_sync(0xffffffffu, w, e2);
            int   s2 = __shfl_sync(0xffffffffu, s, e2);
            float w3 = __shfl_sync(0xffffffffu, w, e3);
            int   s3 = __shfl_sync(0xffffffffu, s, e3);
            uint2 r0 = *(const uint2*)(hh + s0 * 64 + q);
            uint2 r1 = *(const uint2*)(hh + s1 * 64 + q);
            uint2 r2 = *(const uint2*)(hh + s2 * 64 + q);
            uint2 r3 = *(const uint2*)(hh + s3 * 64 + q);
            float2 a0 = __half22float2(*(__half2*)&r0.x), b0 = __half22float2(*(__half2*)&r0.y);
            float2 a1 = __half22float2(*(__half2*)&r1.x), b1 = __half22float2(*(__half2*)&r1.y);
            float2 a2 = __half22float2(*(__half2*)&r2.x), b2 = __half22float2(*(__half2*)&r2.y);
            float2 a3 = __half22float2(*(__half2*)&r3.x), b3 = __half22float2(*(__half2*)&r3.y);
            acc.x += w0 * a0.x + w1 * a1.x + w2 * a2.x + w3 * a3.x;
            acc.y += w0 * a0.y + w1 * a1.y + w2 * a2.y + w3 * a3.y;
            acc.z += w0 * b0.x + w1 * b1.x + w2 * b2.x + w3 * b3.x;
            acc.w += w0 * b0.y + w1 * b1.y + w2 * b2.y + w3 * b3.y;
        }
        for (; p2 < cnt; p2 += 2) {
            int ei = p2 + half;
            int eic = (ei < cnt) ? ei : (cnt - 1);
            float wc = __shfl_sync(0xffffffffu, w, eic);
            int   sc = __shfl_sync(0xffffffffu, s, eic);
            if (ei < cnt) {
                uint2 rv = *(const uint2*)(hh + sc * 64 + q);
                float2 av = __half22float2(*(__half2*)&rv.x);
                float2 bv = __half22float2(*(__half2*)&rv.y);
                acc.x += wc * av.x; acc.y += wc * av.y;
                acc.z += wc * bv.x; acc.w += wc * bv.y;
            }
        }
    }
    acc.x += __shfl_xor_sync(0xffffffffu, acc.x, 16);
    acc.y += __shfl_xor_sync(0xffffffffu, acc.y, 16);
    acc.z += __shfl_xor_sync(0xffffffffu, acc.z, 16);
    acc.w += __shfl_xor_sync(0xffffffffu, acc.w, 16);
#pragma unroll
    for (int off = 16; off; off >>= 1) ssum += __shfl_xor_sync(0xffffffffu, ssum, off);
    float inv = 1.0f / (ssum + 1e-16f);

    float4 b4 = *(const float4*)(bias + q);
    float4 o;
    o.x = acc.x * inv + b4.x; o.y = acc.y * inv + b4.y;
    o.z = acc.z * inv + b4.z; o.w = acc.w * inv + b4.w;

    if (!FINAL) {
        if (half == 0) *(float4*)(out + gw * 64 + q) = o;
    } else {
        float oarr[4] = {o.x, o.y, o.z, o.w};
        float accl = __ldg(&bl[lane]);
#pragma unroll
        for (int k = 0; k < 64; k++) {
            float xk = __shfl_sync(0xffffffffu, oarr[k & 3], k >> 2);
            accl += xk * wsh[k * 32 + lane];
        }
        float mx = accl;
#pragma unroll
        for (int off = 16; off; off >>= 1) mx = fmaxf(mx, __shfl_xor_sync(0xffffffffu, mx, off));
        float ex = __expf(accl - mx);
        float sum = ex;
#pragma unroll
        for (int off = 16; off; off >>= 1) sum += __shfl_xor_sync(0xffffffffu, sum, off);
        out[gw * 32 + lane] = accl - mx - __logf(sum);
    }
}

// ---------------- launch ----------------
extern "C" void kernel_launch(void* const* d_in, const int* in_sizes, int n_in,
                              void* d_out, int out_size) {
    const float* x    = (const float*)d_in[0];
    const int*   ei1  = (const int*)d_in[1];
    const int*   ei2  = (const int*)d_in[2];
    const float* W1   = (const float*)d_in[3];
    const float* as1  = (const float*)d_in[4];
    const float* ad1  = (const float*)d_in[5];
    const float* b1   = (const float*)d_in[6];
    const float* W2   = (const float*)d_in[7];
    const float* as2  = (const float*)d_in[8];
    const float* ad2  = (const float*)d_in[9];
    const float* b2   = (const float*)d_in[10];
    const float* Wlin = (const float*)d_in[11];
    const float* blin = (const float*)d_in[12];
    float* out = (float*)d_out;

    float *h, *o;
    __half* hh;
    int *rowptr, *csr;
    cudaGetSymbolAddress((void**)&h, g_h);
    cudaGetSymbolAddress((void**)&hh, g_hh);
    cudaGetSymbolAddress((void**)&o, g_o);
    cudaGetSymbolAddress((void**)&rowptr, g_rowptr);
    cudaGetSymbolAddress((void**)&csr, g_csr_src);

    static cudaStream_t s1 = nullptr, s2 = nullptr;
    static cudaEvent_t ev_fork = nullptr, ev_csr1 = nullptr, ev_csr2 = nullptr;
    if (s1 == nullptr) {
        cudaStreamCreateWithFlags(&s1, cudaStreamNonBlocking);
        cudaStreamCreateWithFlags(&s2, cudaStreamNonBlocking);
        cudaEventCreateWithFlags(&ev_fork, cudaEventDisableTiming);
        cudaEventCreateWithFlags(&ev_csr1, cudaEventDisableTiming);
        cudaEventCreateWithFlags(&ev_csr2, cudaEventDisableTiming);
    }

    const int gemm_grid = (NN + 63) / 64;
    const int warp_grid = (NN + 7) / 8;
    const int egrid = EE / 256;
    const int ngrid = (NN + 255) / 256;

    // ---- fork: independent CSR chains, one per side stream ----
    cudaEventRecord(ev_fork, 0);
    cudaStreamWaitEvent(s1, ev_fork, 0);
    cudaStreamWaitEvent(s2, ev_fork, 0);

    zero_k<<<ngrid, 256, 0, s1>>>(0);
    hist_k<<<egrid, 256, 0, s1>>>(ei1, 0);
    scan1_k<<<NB_SCAN, 1024, 0, s1>>>(0);
    scan23_k<<<NB_SCAN, 1024, 0, s1>>>(0);
    scatter_k<<<egrid, 256, 0, s1>>>(ei1, 0);
    cudaEventRecord(ev_csr1, s1);

    zero_k<<<ngrid, 256, 0, s2>>>(1);
    hist_k<<<egrid, 256, 0, s2>>>(ei2, 1);
    scan1_k<<<NB_SCAN, 1024, 0, s2>>>(1);
    scan23_k<<<NB_SCAN, 1024, 0, s2>>>(1);
    scatter_k<<<egrid, 256, 0, s2>>>(ei2, 1);
    cudaEventRecord(ev_csr2, s2);

    // ---- main stream ----
    gemm_att<FIN, false><<<gemm_grid, 256>>>(x, W1, h, hh, as1, ad1, NN);
    cudaStreamWaitEvent(0, ev_csr1, 0);
    agg_k<false><<<warp_grid, 256>>>(hh, b1, o, rowptr, csr, nullptr, nullptr);
    gemm_att<HH, true><<<gemm_grid, 256>>>(o, W2, h, hh, as2, ad2, NN);
    cudaStreamWaitEvent(0, ev_csr2, 0);
    agg_k<true><<<warp_grid, 256>>>(hh, b2, out, rowptr + (NN + 1), csr + EE,
                                    Wlin, blin);
}